// round 14
// baseline (speedup 1.0000x reference)
#include <cuda_runtime.h>
#include <cuda_fp16.h>
#include <math.h>
#include <stdint.h>

#define D 1024
#define NH 16
#define HDIM 64
#define NE 64
#define TMAX 16384
#define GH 256

// ============================ device scratch ============================
__device__ __align__(16) float g_k[NE * D];
__device__ __align__(16) float g_v[NE * D];
__device__ __align__(16) float g_sb[D];
__device__ __align__(16) float g_U[GH * D];     // U = W1·Wo
__device__ __align__(16) float g_b1f[GH];       // b1' = W1·opb + b1
__device__ __align__(16) float g_H[TMAX * GH];  // gate hidden (post-gelu, fp32)

// hi/lo fp16 planes
__device__ __align__(16) __half g_xh[(size_t)TMAX * D];
__device__ __align__(16) __half g_xl[(size_t)TMAX * D];
__device__ __align__(16) __half g_Ph[(size_t)TMAX * D];
__device__ __align__(16) __half g_Pl[(size_t)TMAX * D];
__device__ __align__(16) __half g_Awh[(size_t)D * D];
__device__ __align__(16) __half g_Awl[(size_t)D * D];
__device__ __align__(16) __half g_G1h[(size_t)GH * D];
__device__ __align__(16) __half g_G1l[(size_t)GH * D];

// ============================ asm helpers ============================
__device__ __forceinline__ uint32_t smem_u32(const void* p) {
    uint32_t a;
    asm("{ .reg .u64 t; cvta.to.shared.u64 t, %1; cvt.u32.u64 %0, t; }" : "=r"(a) : "l"(p));
    return a;
}
__device__ __forceinline__ void cp16(uint32_t dst, const void* src) {
    asm volatile("cp.async.cg.shared.global [%0], [%1], 16;" :: "r"(dst), "l"(src));
}
#define CP_COMMIT() asm volatile("cp.async.commit_group;" ::: "memory")
#define CP_WAIT2() asm volatile("cp.async.wait_group 2;" ::: "memory")

__device__ __forceinline__ void ldsm4(uint32_t& r0, uint32_t& r1, uint32_t& r2, uint32_t& r3,
                                      uint32_t addr) {
    asm volatile("ldmatrix.sync.aligned.m8n8.x4.shared.b16 {%0,%1,%2,%3}, [%4];"
                 : "=r"(r0), "=r"(r1), "=r"(r2), "=r"(r3) : "r"(addr));
}
__device__ __forceinline__ void mma16816(float* c, const uint32_t* a, const uint32_t* b) {
    asm volatile(
        "mma.sync.aligned.m16n8k16.row.col.f32.f16.f16.f32 "
        "{%0,%1,%2,%3}, {%4,%5,%6,%7}, {%8,%9}, {%0,%1,%2,%3};"
        : "+f"(c[0]), "+f"(c[1]), "+f"(c[2]), "+f"(c[3])
        : "r"(a[0]), "r"(a[1]), "r"(a[2]), "r"(a[3]), "r"(b[0]), "r"(b[1]));
}
__device__ __forceinline__ uint32_t packh2(__half a, __half b) {
    __half2 t; t.x = a; t.y = b;
    return *reinterpret_cast<uint32_t*>(&t);
}
// smem swizzle: row stride 64B (32 halves), chunk = 16B unit index 0..3
__device__ __forceinline__ uint32_t swz(uint32_t row, uint32_t chunk) {
    return row * 64u + ((chunk ^ ((row >> 1) & 3u)) * 16u);
}

// ============================ precompute kernels ============================
// kv v2: coalesced via smem staging.
__global__ __launch_bounds__(256) void kv_kernel(const float* __restrict__ emb,
                          const float* __restrict__ wk, const float* __restrict__ bk,
                          const float* __restrict__ wv, const float* __restrict__ bv) {
    __shared__ float sk[4][D];
    __shared__ float sv[4][D];
    __shared__ float tile[64][65];
    const int tid = threadIdx.x;
    const int j0 = blockIdx.x * 4;
    for (int i = tid; i < 4 * (D / 4); i += 256) {
        int r = i / (D / 4), c = i % (D / 4);
        ((float4*)sk[r])[c] = ((const float4*)(wk + (size_t)(j0 + r) * D))[c];
        ((float4*)sv[r])[c] = ((const float4*)(wv + (size_t)(j0 + r) * D))[c];
    }
    const int e = tid & 63, js = tid >> 6;
    float ak = 0.f, av = 0.f;
    for (int d0 = 0; d0 < D; d0 += 64) {
        __syncthreads();
        for (int idx = tid; idx < 64 * 64; idx += 256) {
            int r = idx >> 6, c = idx & 63;
            tile[r][c] = emb[(size_t)r * D + d0 + c];
        }
        __syncthreads();
#pragma unroll 16
        for (int dd = 0; dd < 64; dd++) {
            float xv = tile[e][dd];
            ak = fmaf(xv, sk[js][d0 + dd], ak);
            av = fmaf(xv, sv[js][d0 + dd], av);
        }
    }
    const int j = j0 + js;
    g_k[e * D + j] = ak + bk[j];
    g_v[e * D + j] = av + bv[j];
}

// buildA v2: block = (dblk 0..15, h 0..15); Wq tile read ONCE; 64x64x64 mini-GEMM.
// A[(h,e)][d] = 0.125 * sum_hd wq[h*64+hd][d] * k[e][h*64+hd]; writes hi/lo planes.
__global__ __launch_bounds__(256) void buildA_kernel(const float* __restrict__ wq,
                                                     const float* __restrict__ bq) {
    __shared__ float wqs[64][65];   // [hd][d-local]
    __shared__ float kt[64][68];    // [hd][e]
    __shared__ float bqs[64];
    const int tid = threadIdx.x;
    const int d0 = blockIdx.x * 64;
    const int h = blockIdx.y;

    // load wq tile: rows h*64..+63, cols d0..d0+63  (coalesced over d)
    for (int i = tid; i < 64 * 64; i += 256) {
        int hd = i >> 6, d = i & 63;
        wqs[hd][d] = wq[(size_t)(h * HDIM + hd) * D + d0 + d];
    }
    // load k tile transposed: kt[hd][e] = g_k[e*D + h*64+hd]  (coalesced over hd)
    for (int i = tid; i < 64 * 64; i += 256) {
        int e = i >> 6, hd = i & 63;
        kt[hd][e] = g_k[(size_t)e * D + h * HDIM + hd];
    }
    if (tid < 64) bqs[tid] = bq[h * HDIM + tid];
    __syncthreads();

    // each thread: 4 e x 4 d outputs
    const int tx = tid & 15, ty = tid >> 4;
    const int eb = ty * 4, db = tx * 4;
    float acc[4][4] = {};
#pragma unroll 16
    for (int hd = 0; hd < 64; hd++) {
        float kv0 = kt[hd][eb], kv1 = kt[hd][eb + 1], kv2 = kt[hd][eb + 2], kv3 = kt[hd][eb + 3];
        float w0 = wqs[hd][db], w1 = wqs[hd][db + 1], w2 = wqs[hd][db + 2], w3 = wqs[hd][db + 3];
        acc[0][0] = fmaf(kv0, w0, acc[0][0]); acc[0][1] = fmaf(kv0, w1, acc[0][1]);
        acc[0][2] = fmaf(kv0, w2, acc[0][2]); acc[0][3] = fmaf(kv0, w3, acc[0][3]);
        acc[1][0] = fmaf(kv1, w0, acc[1][0]); acc[1][1] = fmaf(kv1, w1, acc[1][1]);
        acc[1][2] = fmaf(kv1, w2, acc[1][2]); acc[1][3] = fmaf(kv1, w3, acc[1][3]);
        acc[2][0] = fmaf(kv2, w0, acc[2][0]); acc[2][1] = fmaf(kv2, w1, acc[2][1]);
        acc[2][2] = fmaf(kv2, w2, acc[2][2]); acc[2][3] = fmaf(kv2, w3, acc[2][3]);
        acc[3][0] = fmaf(kv3, w0, acc[3][0]); acc[3][1] = fmaf(kv3, w1, acc[3][1]);
        acc[3][2] = fmaf(kv3, w2, acc[3][2]); acc[3][3] = fmaf(kv3, w3, acc[3][3]);
    }
#pragma unroll
    for (int i = 0; i < 4; i++) {
        int he = h * 64 + eb + i;
#pragma unroll
        for (int j = 0; j < 4; j++) {
            float a = acc[i][j] * 0.125f;
            __half hh = __float2half_rn(a);
            g_Awh[(size_t)he * D + d0 + db + j] = hh;
            g_Awl[(size_t)he * D + d0 + db + j] = __float2half_rn(a - __half2float(hh));
        }
    }
    // bias (once per h)
    if (blockIdx.x == 0 && tid < 64) {
        float acc2 = 0.f;
#pragma unroll
        for (int hd = 0; hd < 64; hd++) acc2 = fmaf(bqs[hd], kt[hd][tid], acc2);
        g_sb[h * 64 + tid] = acc2 * 0.125f;
    }
}

// U = W1·Wo (256x1024):  U[g][din] = sum_dout W1[g][dout]*wo[dout][din]
__global__ __launch_bounds__(256) void u_kernel(const float* __restrict__ W1,
                                                const float* __restrict__ wo) {
    __shared__ float w1s[16][33];
    const int din = blockIdx.x * 128 + (threadIdx.x & 127);
    const int gy = threadIdx.x >> 7;   // 0..1
    const int g0 = blockIdx.y * 16;
    float acc[8] = {};
    for (int d0 = 0; d0 < D; d0 += 32) {
        for (int i = threadIdx.x; i < 16 * 32; i += 256) {
            int r = i >> 5, c = i & 31;
            w1s[r][c] = W1[(size_t)(g0 + r) * D + d0 + c];
        }
        __syncthreads();
#pragma unroll 8
        for (int dd = 0; dd < 32; dd++) {
            float mv = wo[(size_t)(d0 + dd) * D + din];
#pragma unroll
            for (int j = 0; j < 8; j++)
                acc[j] = fmaf(w1s[gy * 8 + j][dd], mv, acc[j]);
        }
        __syncthreads();
    }
#pragma unroll
    for (int j = 0; j < 8; j++)
        g_U[(size_t)(g0 + gy * 8 + j) * D + din] = acc[j];
}

// G1[g][(h,e)] = sum_hd U[g][h*64+hd]*v[e][h*64+hd] -> hi/lo planes. One block per g.
__global__ __launch_bounds__(256) void g1v_kernel() {
    __shared__ float Us[D];
    const int g = blockIdx.x;
    for (int i = threadIdx.x; i < D / 4; i += 256)
        ((float4*)Us)[i] = ((const float4*)(g_U + (size_t)g * D))[i];
    __syncthreads();
    const int wid = threadIdx.x >> 5, lane = threadIdx.x & 31;
    for (int he = wid; he < D; he += 8) {
        int h = he >> 6, e = he & 63;
        const float* vp = g_v + (size_t)e * D + h * HDIM;
        const float* up = Us + h * HDIM;
        float a = vp[lane] * up[lane] + vp[lane + 32] * up[lane + 32];
#pragma unroll
        for (int o = 16; o; o >>= 1) a += __shfl_xor_sync(0xffffffffu, a, o);
        if (lane == 0) {
            __half hh = __float2half_rn(a);
            g_G1h[(size_t)g * D + he] = hh;
            g_G1l[(size_t)g * D + he] = __float2half_rn(a - __half2float(hh));
        }
    }
}

// b1'[g] = b1[g] + sum_d W1[g][d]*opb[d]
__global__ void b1fold_kernel(const float* __restrict__ W1, const float* __restrict__ opb,
                              const float* __restrict__ b1) {
    int wid = threadIdx.x >> 5, lane = threadIdx.x & 31;
    int g = blockIdx.x * 8 + wid;
    float acc = 0.f;
    for (int d = lane; d < D; d += 32) acc = fmaf(W1[(size_t)g * D + d], opb[d], acc);
#pragma unroll
    for (int o = 16; o; o >>= 1) acc += __shfl_xor_sync(0xffffffffu, acc, o);
    if (lane == 0) g_b1f[g] = acc + b1[g];
}

// ============================ fp32 -> fp16 hi/lo planes ============================
__global__ void split_kernel(const float* __restrict__ in,
                             __half* __restrict__ hi, __half* __restrict__ lo, int n4) {
    int i = blockIdx.x * blockDim.x + threadIdx.x;
    if (i >= n4) return;
    float4 v = ((const float4*)in)[i];
    __half h0 = __float2half_rn(v.x), h1 = __float2half_rn(v.y);
    __half h2 = __float2half_rn(v.z), h3 = __float2half_rn(v.w);
    __half l0 = __float2half_rn(v.x - __half2float(h0));
    __half l1 = __float2half_rn(v.y - __half2float(h1));
    __half l2 = __float2half_rn(v.z - __half2float(h2));
    __half l3 = __float2half_rn(v.w - __half2float(h3));
    uint2 Hh, Ll;
    Hh.x = packh2(h0, h1); Hh.y = packh2(h2, h3);
    Ll.x = packh2(l0, l1); Ll.y = packh2(l2, l3);
    ((uint2*)hi)[i] = Hh;
    ((uint2*)lo)[i] = Ll;
}

// ============================ HMMA GEMM (R8/R13 measured-best) ============================
constexpr int BM = 128, BN = 128, BK = 32, STAGES = 4;
constexpr int KD = 1024, KE = 3 * KD;
constexpr int ASTG = BM * BK * 2;
constexpr int BSTG = BN * BK * 2;
constexpr int STG = ASTG + BSTG;
constexpr int HG_SMEM = STAGES * STG;    // 65536

__device__ __forceinline__ void load_stage(uint32_t sbase,
        const __half* __restrict__ Ahi, const __half* __restrict__ Alo,
        const __half* __restrict__ Bhi, const __half* __restrict__ Blo,
        int bm, int bn, int k0, int tid) {
    const int p = k0 >> 10;
    const int ko = k0 & (KD - 1);
    const __half* __restrict__ Asrc = (p == 2) ? Alo : Ahi;   // A-pattern hi,hi,lo
    const __half* __restrict__ Bsrc = (p == 1) ? Blo : Bhi;   // B-pattern hi,lo,hi
#pragma unroll
    for (int i = 0; i < 4; i++) {
        int idx = tid + i * 128;
        int row = idx >> 2, c = idx & 3;
        cp16(sbase + swz(row, c), Asrc + (size_t)(bm + row) * KD + ko + c * 8);
    }
#pragma unroll
    for (int i = 0; i < 4; i++) {
        int idx = tid + i * 128;
        int row = idx >> 2, c = idx & 3;
        cp16(sbase + ASTG + swz(row, c), Bsrc + (size_t)(bn + row) * KD + ko + c * 8);
    }
}

// EPI 0: +bias -> softmax(64-col groups) -> hi/lo planes; EPI 2: +bias -> gelu -> fp32
template <int EPI>
__global__ __launch_bounds__(128, 2)
void hgemm(const __half* __restrict__ Ahi, const __half* __restrict__ Alo,
           const __half* __restrict__ Bhi, const __half* __restrict__ Blo,
           const float* __restrict__ bias,
           __half* __restrict__ Ohi, __half* __restrict__ Olo,
           float* __restrict__ Of32, int Nout) {
    extern __shared__ char smraw[];
    const uint32_t sbase = smem_u32(smraw);
    const int tid = threadIdx.x;
    const int lane = tid & 31, wid = tid >> 5;
    const int wm = wid & 1, wn = wid >> 1;
    const int bm = blockIdx.y * BM, bn = blockIdx.x * BN;

    float acc[4][8][4] = {};
    constexpr int KT = KE / BK;   // 96

#pragma unroll
    for (int s = 0; s < STAGES - 1; s++) {
        load_stage(sbase + s * STG, Ahi, Alo, Bhi, Blo, bm, bn, s * BK, tid);
        CP_COMMIT();
    }

    for (int it = 0; it < KT; it++) {
        CP_WAIT2();
        __syncthreads();
        int nit = it + STAGES - 1;
        if (nit < KT)
            load_stage(sbase + (nit & (STAGES - 1)) * STG, Ahi, Alo, Bhi, Blo,
                       bm, bn, nit * BK, tid);
        CP_COMMIT();

        uint32_t sA = sbase + (it & (STAGES - 1)) * STG;
        uint32_t sB = sA + ASTG;
#pragma unroll
        for (int ks = 0; ks < 2; ks++) {
            uint32_t af[4][4];
#pragma unroll
            for (int mt = 0; mt < 4; mt++) {
                uint32_t row = wm * 64 + mt * 16 + (lane & 15);
                uint32_t ch = ks * 2 + (lane >> 4);
                ldsm4(af[mt][0], af[mt][1], af[mt][2], af[mt][3], sA + swz(row, ch));
            }
            uint32_t bf[4][4];
#pragma unroll
            for (int np = 0; np < 4; np++) {
                uint32_t row = wn * 64 + np * 16 + (lane & 7) + ((lane >> 4) & 1) * 8;
                uint32_t ch = ks * 2 + ((lane >> 3) & 1);
                ldsm4(bf[np][0], bf[np][1], bf[np][2], bf[np][3], sB + swz(row, ch));
            }
#pragma unroll
            for (int mt = 0; mt < 4; mt++)
#pragma unroll
                for (int nt = 0; nt < 8; nt++)
                    mma16816(acc[mt][nt], af[mt], &bf[nt >> 1][(nt & 1) * 2]);
        }
    }

    // ---------------- epilogue ----------------
    const int colb = bn + wn * 64;
    float bv[16];
#pragma unroll
    for (int nt = 0; nt < 8; nt++) {
        int c = colb + nt * 8 + (lane & 3) * 2;
        bv[nt * 2] = bias[c];
        bv[nt * 2 + 1] = bias[c + 1];
    }

#pragma unroll
    for (int mt = 0; mt < 4; mt++) {
#pragma unroll
        for (int h = 0; h < 2; h++) {
            int row = bm + wm * 64 + mt * 16 + (lane >> 2) + h * 8;
            float v[16];
#pragma unroll
            for (int nt = 0; nt < 8; nt++) {
                v[nt * 2] = acc[mt][nt][h * 2] + bv[nt * 2];
                v[nt * 2 + 1] = acc[mt][nt][h * 2 + 1] + bv[nt * 2 + 1];
            }
            if (EPI == 0) {
                float m = v[0];
#pragma unroll
                for (int j = 1; j < 16; j++) m = fmaxf(m, v[j]);
                m = fmaxf(m, __shfl_xor_sync(0xffffffffu, m, 1));
                m = fmaxf(m, __shfl_xor_sync(0xffffffffu, m, 2));
                float s = 0.f;
#pragma unroll
                for (int j = 0; j < 16; j++) { v[j] = expf(v[j] - m); s += v[j]; }
                s += __shfl_xor_sync(0xffffffffu, s, 1);
                s += __shfl_xor_sync(0xffffffffu, s, 2);
                float inv = 1.0f / s;
#pragma unroll
                for (int j = 0; j < 16; j++) v[j] *= inv;
            }
            if (EPI == 2) {
#pragma unroll
                for (int j = 0; j < 16; j++)
                    v[j] = 0.5f * v[j] * (1.0f + erff(v[j] * 0.70710678118654752f));
            }
            if (EPI == 2) {
                float* op = Of32 + (size_t)row * Nout;
#pragma unroll
                for (int nt = 0; nt < 8; nt++) {
                    int c = colb + nt * 8 + (lane & 3) * 2;
                    float2 f2; f2.x = v[nt * 2]; f2.y = v[nt * 2 + 1];
                    *(float2*)(op + c) = f2;
                }
            } else {
                __half* oh = Ohi + (size_t)row * Nout;
                __half* ol = Olo + (size_t)row * Nout;
#pragma unroll
                for (int nt = 0; nt < 8; nt++) {
                    int c = colb + nt * 8 + (lane & 3) * 2;
                    float a = v[nt * 2], b = v[nt * 2 + 1];
                    __half ha = __float2half_rn(a), hb = __float2half_rn(b);
                    __half la = __float2half_rn(a - __half2float(ha));
                    __half lb = __float2half_rn(b - __half2float(hb));
                    *(uint32_t*)(oh + c) = packh2(ha, hb);
                    *(uint32_t*)(ol + c) = packh2(la, lb);
                }
            }
        }
    }
}

// ============================ fused logits + top-2 ============================
__device__ __forceinline__ bool better(float va, int ia, float vb, int ib) {
    return (va > vb) || (va == vb && ia < ib);
}

__global__ __launch_bounds__(256)
void logits_topk_kernel(const float* __restrict__ Hm, const float* __restrict__ W2,
                        const float* __restrict__ b2, float* __restrict__ out, int T) {
    extern __shared__ float w2s[];     // [GH][NE] = 64KB
    __shared__ float b2s[NE];
    for (int i = threadIdx.x; i < NE * GH; i += 256) {
        int e = i >> 8, k = i & (GH - 1);
        w2s[k * NE + e] = W2[i];
    }
    if (threadIdx.x < NE) b2s[threadIdx.x] = b2[threadIdx.x];
    __syncthreads();

    const int wid = threadIdx.x >> 5, lane = threadIdx.x & 31;
#pragma unroll 1
    for (int ti = 0; ti < 16; ti++) {
        const int t = blockIdx.x * 128 + wid * 16 + ti;
        const float* hrow = Hm + (size_t)t * GH;
        float a0 = b2s[lane], a1 = b2s[lane + 32];
#pragma unroll 4
        for (int k4 = 0; k4 < GH / 4; k4++) {
            float4 hv = ((const float4*)hrow)[k4];
            const float* wp = w2s + (k4 * 4) * NE;
            a0 = fmaf(hv.x, wp[lane], a0);
            a1 = fmaf(hv.x, wp[lane + 32], a1);
            a0 = fmaf(hv.y, wp[NE + lane], a0);
            a1 = fmaf(hv.y, wp[NE + lane + 32], a1);
            a0 = fmaf(hv.z, wp[2 * NE + lane], a0);
            a1 = fmaf(hv.z, wp[2 * NE + lane + 32], a1);
            a0 = fmaf(hv.w, wp[3 * NE + lane], a0);
            a1 = fmaf(hv.w, wp[3 * NE + lane + 32], a1);
        }
        float m = fmaxf(a0, a1);
#pragma unroll
        for (int o = 16; o; o >>= 1) m = fmaxf(m, __shfl_xor_sync(0xffffffffu, m, o));
        float Z = expf(a0 - m) + expf(a1 - m);
#pragma unroll
        for (int o = 16; o; o >>= 1) Z += __shfl_xor_sync(0xffffffffu, Z, o);

        float v1, v2; int i1, i2;
        if (a1 > a0) { v1 = a1; i1 = lane + 32; v2 = a0; i2 = lane; }
        else         { v1 = a0; i1 = lane;      v2 = a1; i2 = lane + 32; }
#pragma unroll
        for (int o = 16; o; o >>= 1) {
            float w1 = __shfl_xor_sync(0xffffffffu, v1, o);
            int   j1 = __shfl_xor_sync(0xffffffffu, i1, o);
            float w2v = __shfl_xor_sync(0xffffffffu, v2, o);
            int   j2 = __shfl_xor_sync(0xffffffffu, i2, o);
            if (better(w1, j1, v1, i1)) {
                if (better(v1, i1, w2v, j2)) { v2 = v1; i2 = i1; }
                else                         { v2 = w2v; i2 = j2; }
                v1 = w1; i1 = j1;
            } else {
                if (better(w1, j1, v2, i2)) { v2 = w1; i2 = j1; }
            }
        }
        if (lane == 0) {
            float p1 = expf(v1 - m) / Z;
            float p2 = expf(v2 - m) / Z;
            float denom = p1 + p2 + 1e-8f;
            out[(size_t)t * 2 + 0] = (float)i1;
            out[(size_t)t * 2 + 1] = (float)i2;
            out[(size_t)2 * T + (size_t)t * 2 + 0] = p1 / denom;
            out[(size_t)2 * T + (size_t)t * 2 + 1] = p2 / denom;
        }
    }
}

// ============================ launch ============================
extern "C" void kernel_launch(void* const* d_in, const int* in_sizes, int n_in,
                              void* d_out, int out_size) {
    const float* x   = (const float*)d_in[0];
    const float* emb = (const float*)d_in[1];
    const float* ipw = (const float*)d_in[2];
    const float* ipb = (const float*)d_in[3];
    const float* opw = (const float*)d_in[4];
    const float* opb = (const float*)d_in[5];
    const float* gw1 = (const float*)d_in[6];
    const float* gb1 = (const float*)d_in[7];
    const float* gw2 = (const float*)d_in[8];
    const float* gb2 = (const float*)d_in[9];

    const int T = in_sizes[0] / D;

    cudaFuncSetAttribute(hgemm<0>, cudaFuncAttributeMaxDynamicSharedMemorySize, HG_SMEM);
    cudaFuncSetAttribute(hgemm<2>, cudaFuncAttributeMaxDynamicSharedMemorySize, HG_SMEM);
    const int LT_SMEM = NE * GH * 4;
    cudaFuncSetAttribute(logits_topk_kernel, cudaFuncAttributeMaxDynamicSharedMemorySize, LT_SMEM);

    float *psb, *pb1f, *pH;
    cudaGetSymbolAddress((void**)&psb,  g_sb);
    cudaGetSymbolAddress((void**)&pb1f, g_b1f);
    cudaGetSymbolAddress((void**)&pH,   g_H);
    __half *pxh, *pxl, *pPh, *pPl, *pAwh, *pAwl, *pG1h, *pG1l;
    cudaGetSymbolAddress((void**)&pxh,  g_xh);
    cudaGetSymbolAddress((void**)&pxl,  g_xl);
    cudaGetSymbolAddress((void**)&pPh,  g_Ph);
    cudaGetSymbolAddress((void**)&pPl,  g_Pl);
    cudaGetSymbolAddress((void**)&pAwh, g_Awh);
    cudaGetSymbolAddress((void**)&pAwl, g_Awl);
    cudaGetSymbolAddress((void**)&pG1h, g_G1h);
    cudaGetSymbolAddress((void**)&pG1l, g_G1l);

    // 0: kv   1: U=W1·Wo   2: split x   3: buildA(v2)  <- ncu lands on idx 3
    kv_kernel<<<D / 4, 256>>>(emb, ipw + (size_t)D * D, ipb + D,
                              ipw + (size_t)2 * D * D, ipb + 2 * D);
    u_kernel<<<dim3(D / 128, GH / 16), 256>>>(gw1, opw);
    split_kernel<<<(T * D / 4 + 255) / 256, 256>>>(x, pxh, pxl, T * D / 4);
    buildA_kernel<<<dim3(16, 16), 256>>>(ipw, ipb);

    // 4: GEMM1: scores = x·A^T + sb -> softmax(64) -> P planes
    hgemm<0><<<dim3(D / BN, T / BM), 128, HG_SMEM>>>(
        pxh, pxl, pAwh, pAwl, psb, pPh, pPl, nullptr, D);

    // 5-6: G1 from U and v; folded bias
    g1v_kernel<<<GH, 256>>>();
    b1fold_kernel<<<GH / 8, 256>>>(gw1, opb, gb1);

    // 7: H = gelu(P·G1^T + b1') -> fp32
    hgemm<2><<<dim3(GH / BN, T / BM), 128, HG_SMEM>>>(
        pPh, pPl, pG1h, pG1l, pb1f, nullptr, nullptr, pH, GH);

    // 8: logits + softmax + top-2 fused
    logits_topk_kernel<<<T / 128, 256, LT_SMEM>>>(pH, gw2, gb2, (float*)d_out, T);
}

// round 15
// speedup vs baseline: 1.0982x; 1.0982x over previous
#include <cuda_runtime.h>
#include <cuda_fp16.h>
#include <math.h>
#include <stdint.h>

#define D 1024
#define NH 16
#define HDIM 64
#define NE 64
#define TMAX 16384
#define GH 256

// ============================ device scratch ============================
__device__ __align__(16) float g_k[NE * D];
__device__ __align__(16) float g_v[NE * D];
__device__ __align__(16) float g_sb[D];
__device__ __align__(16) float g_MT[D * D];     // MT[dout][(h,e)]
__device__ __align__(16) float g_b1f[GH];       // b1' = W1·opb + b1
__device__ __align__(16) float g_H[TMAX * GH];  // gate hidden (post-gelu, fp32)

// hi/lo fp16 planes
__device__ __align__(16) __half g_xh[(size_t)TMAX * D];
__device__ __align__(16) __half g_xl[(size_t)TMAX * D];
__device__ __align__(16) __half g_Ph[(size_t)TMAX * D];
__device__ __align__(16) __half g_Pl[(size_t)TMAX * D];
__device__ __align__(16) __half g_Awh[(size_t)D * D];
__device__ __align__(16) __half g_Awl[(size_t)D * D];
__device__ __align__(16) __half g_G1h[(size_t)GH * D];
__device__ __align__(16) __half g_G1l[(size_t)GH * D];

// ============================ asm helpers ============================
__device__ __forceinline__ uint32_t smem_u32(const void* p) {
    uint32_t a;
    asm("{ .reg .u64 t; cvta.to.shared.u64 t, %1; cvt.u32.u64 %0, t; }" : "=r"(a) : "l"(p));
    return a;
}
__device__ __forceinline__ void cp16(uint32_t dst, const void* src) {
    asm volatile("cp.async.cg.shared.global [%0], [%1], 16;" :: "r"(dst), "l"(src));
}
#define CP_COMMIT() asm volatile("cp.async.commit_group;" ::: "memory")
#define CP_WAIT2() asm volatile("cp.async.wait_group 2;" ::: "memory")

__device__ __forceinline__ void ldsm4(uint32_t& r0, uint32_t& r1, uint32_t& r2, uint32_t& r3,
                                      uint32_t addr) {
    asm volatile("ldmatrix.sync.aligned.m8n8.x4.shared.b16 {%0,%1,%2,%3}, [%4];"
                 : "=r"(r0), "=r"(r1), "=r"(r2), "=r"(r3) : "r"(addr));
}
__device__ __forceinline__ void mma16816(float* c, const uint32_t* a, const uint32_t* b) {
    asm volatile(
        "mma.sync.aligned.m16n8k16.row.col.f32.f16.f16.f32 "
        "{%0,%1,%2,%3}, {%4,%5,%6,%7}, {%8,%9}, {%0,%1,%2,%3};"
        : "+f"(c[0]), "+f"(c[1]), "+f"(c[2]), "+f"(c[3])
        : "r"(a[0]), "r"(a[1]), "r"(a[2]), "r"(a[3]), "r"(b[0]), "r"(b[1]));
}
__device__ __forceinline__ uint32_t packh2(__half a, __half b) {
    __half2 t; t.x = a; t.y = b;
    return *reinterpret_cast<uint32_t*>(&t);
}
// smem swizzle: row stride 64B (32 halves), chunk = 16B unit index 0..3
__device__ __forceinline__ uint32_t swz(uint32_t row, uint32_t chunk) {
    return row * 64u + ((chunk ^ ((row >> 1) & 3u)) * 16u);
}

// ============================ precompute kernels ============================
// kv v2: coalesced via smem staging.
__global__ __launch_bounds__(256) void kv_kernel(const float* __restrict__ emb,
                          const float* __restrict__ wk, const float* __restrict__ bk,
                          const float* __restrict__ wv, const float* __restrict__ bv) {
    __shared__ float sk[4][D];
    __shared__ float sv[4][D];
    __shared__ float tile[64][65];
    const int tid = threadIdx.x;
    const int j0 = blockIdx.x * 4;
    for (int i = tid; i < 4 * (D / 4); i += 256) {
        int r = i / (D / 4), c = i % (D / 4);
        ((float4*)sk[r])[c] = ((const float4*)(wk + (size_t)(j0 + r) * D))[c];
        ((float4*)sv[r])[c] = ((const float4*)(wv + (size_t)(j0 + r) * D))[c];
    }
    const int e = tid & 63, js = tid >> 6;
    float ak = 0.f, av = 0.f;
    for (int d0 = 0; d0 < D; d0 += 64) {
        __syncthreads();
        for (int idx = tid; idx < 64 * 64; idx += 256) {
            int r = idx >> 6, c = idx & 63;
            tile[r][c] = emb[(size_t)r * D + d0 + c];
        }
        __syncthreads();
#pragma unroll 16
        for (int dd = 0; dd < 64; dd++) {
            float xv = tile[e][dd];
            ak = fmaf(xv, sk[js][d0 + dd], ak);
            av = fmaf(xv, sv[js][d0 + dd], av);
        }
    }
    const int j = j0 + js;
    g_k[e * D + j] = ak + bk[j];
    g_v[e * D + j] = av + bv[j];
}

// buildA v2: block = (dblk 0..15, h 0..15); Wq tile read ONCE; 64x64x64 mini-GEMM.
__global__ __launch_bounds__(256) void buildA_kernel(const float* __restrict__ wq,
                                                     const float* __restrict__ bq) {
    __shared__ float wqs[64][65];   // [hd][d-local]
    __shared__ float kt[64][68];    // [hd][e]
    __shared__ float bqs[64];
    const int tid = threadIdx.x;
    const int d0 = blockIdx.x * 64;
    const int h = blockIdx.y;

    for (int i = tid; i < 64 * 64; i += 256) {
        int hd = i >> 6, d = i & 63;
        wqs[hd][d] = wq[(size_t)(h * HDIM + hd) * D + d0 + d];
    }
    for (int i = tid; i < 64 * 64; i += 256) {
        int e = i >> 6, hd = i & 63;
        kt[hd][e] = g_k[(size_t)e * D + h * HDIM + hd];
    }
    if (tid < 64) bqs[tid] = bq[h * HDIM + tid];
    __syncthreads();

    const int tx = tid & 15, ty = tid >> 4;
    const int eb = ty * 4, db = tx * 4;
    float acc[4][4] = {};
#pragma unroll 16
    for (int hd = 0; hd < 64; hd++) {
        float kv0 = kt[hd][eb], kv1 = kt[hd][eb + 1], kv2 = kt[hd][eb + 2], kv3 = kt[hd][eb + 3];
        float w0 = wqs[hd][db], w1 = wqs[hd][db + 1], w2 = wqs[hd][db + 2], w3 = wqs[hd][db + 3];
        acc[0][0] = fmaf(kv0, w0, acc[0][0]); acc[0][1] = fmaf(kv0, w1, acc[0][1]);
        acc[0][2] = fmaf(kv0, w2, acc[0][2]); acc[0][3] = fmaf(kv0, w3, acc[0][3]);
        acc[1][0] = fmaf(kv1, w0, acc[1][0]); acc[1][1] = fmaf(kv1, w1, acc[1][1]);
        acc[1][2] = fmaf(kv1, w2, acc[1][2]); acc[1][3] = fmaf(kv1, w3, acc[1][3]);
        acc[2][0] = fmaf(kv2, w0, acc[2][0]); acc[2][1] = fmaf(kv2, w1, acc[2][1]);
        acc[2][2] = fmaf(kv2, w2, acc[2][2]); acc[2][3] = fmaf(kv2, w3, acc[2][3]);
        acc[3][0] = fmaf(kv3, w0, acc[3][0]); acc[3][1] = fmaf(kv3, w1, acc[3][1]);
        acc[3][2] = fmaf(kv3, w2, acc[3][2]); acc[3][3] = fmaf(kv3, w3, acc[3][3]);
    }
#pragma unroll
    for (int i = 0; i < 4; i++) {
        int he = h * 64 + eb + i;
#pragma unroll
        for (int j = 0; j < 4; j++) {
            float a = acc[i][j] * 0.125f;
            __half hh = __float2half_rn(a);
            g_Awh[(size_t)he * D + d0 + db + j] = hh;
            g_Awl[(size_t)he * D + d0 + db + j] = __float2half_rn(a - __half2float(hh));
        }
    }
    if (blockIdx.x == 0 && tid < 64) {
        float acc2 = 0.f;
#pragma unroll
        for (int hd = 0; hd < 64; hd++) acc2 = fmaf(bqs[hd], kt[hd][tid], acc2);
        g_sb[h * 64 + tid] = acc2 * 0.125f;
    }
}

// MT[dout][(h,e)] — warp-per-he, lane indexes hd -> coalesced v reads.
__global__ __launch_bounds__(256) void buildMT_kernel(const float* __restrict__ wo) {
    int dout = blockIdx.x;
    __shared__ float wrow[D];
    for (int i = threadIdx.x; i < D / 4; i += 256)
        ((float4*)wrow)[i] = ((const float4*)(wo + (size_t)dout * D))[i];
    __syncthreads();
    const int wid = threadIdx.x >> 5, lane = threadIdx.x & 31;
    for (int he = wid; he < D; he += 8) {
        int h = he >> 6, e = he & 63;
        const float* vp = g_v + (size_t)e * D + h * HDIM;
        const float* wp = wrow + h * HDIM;
        float a = vp[lane] * wp[lane] + vp[lane + 32] * wp[lane + 32];
#pragma unroll
        for (int o = 16; o; o >>= 1) a += __shfl_xor_sync(0xffffffffu, a, o);
        if (lane == 0) g_MT[(size_t)dout * D + he] = a;
    }
}

// G1 = W1·MT (256x1024), written directly as hi/lo planes.
__global__ __launch_bounds__(256) void g1_kernel(const float* __restrict__ W1) {
    __shared__ float w1s[16][33];
    const int he = blockIdx.x * 128 + (threadIdx.x & 127);
    const int gy = threadIdx.x >> 7;   // 0..1
    const int g0 = blockIdx.y * 16;
    float acc[8] = {};
    for (int d0 = 0; d0 < D; d0 += 32) {
        for (int i = threadIdx.x; i < 16 * 32; i += 256) {
            int r = i >> 5, c = i & 31;
            w1s[r][c] = W1[(size_t)(g0 + r) * D + d0 + c];
        }
        __syncthreads();
#pragma unroll 8
        for (int dd = 0; dd < 32; dd++) {
            float mv = g_MT[(size_t)(d0 + dd) * D + he];
#pragma unroll
            for (int j = 0; j < 8; j++)
                acc[j] = fmaf(w1s[gy * 8 + j][dd], mv, acc[j]);
        }
        __syncthreads();
    }
#pragma unroll
    for (int j = 0; j < 8; j++) {
        float a = acc[j];
        __half hh = __float2half_rn(a);
        g_G1h[(size_t)(g0 + gy * 8 + j) * D + he] = hh;
        g_G1l[(size_t)(g0 + gy * 8 + j) * D + he] = __float2half_rn(a - __half2float(hh));
    }
}

// b1'[g] = b1[g] + sum_d W1[g][d]*opb[d]
__global__ void b1fold_kernel(const float* __restrict__ W1, const float* __restrict__ opb,
                              const float* __restrict__ b1) {
    int wid = threadIdx.x >> 5, lane = threadIdx.x & 31;
    int g = blockIdx.x * 8 + wid;
    float acc = 0.f;
    for (int d = lane; d < D; d += 32) acc = fmaf(W1[(size_t)g * D + d], opb[d], acc);
#pragma unroll
    for (int o = 16; o; o >>= 1) acc += __shfl_xor_sync(0xffffffffu, acc, o);
    if (lane == 0) g_b1f[g] = acc + b1[g];
}

// ============================ fp32 -> fp16 hi/lo planes ============================
__global__ void split_kernel(const float* __restrict__ in,
                             __half* __restrict__ hi, __half* __restrict__ lo, int n4) {
    int i = blockIdx.x * blockDim.x + threadIdx.x;
    if (i >= n4) return;
    float4 v = ((const float4*)in)[i];
    __half h0 = __float2half_rn(v.x), h1 = __float2half_rn(v.y);
    __half h2 = __float2half_rn(v.z), h3 = __float2half_rn(v.w);
    __half l0 = __float2half_rn(v.x - __half2float(h0));
    __half l1 = __float2half_rn(v.y - __half2float(h1));
    __half l2 = __float2half_rn(v.z - __half2float(h2));
    __half l3 = __float2half_rn(v.w - __half2float(h3));
    uint2 Hh, Ll;
    Hh.x = packh2(h0, h1); Hh.y = packh2(h2, h3);
    Ll.x = packh2(l0, l1); Ll.y = packh2(l2, l3);
    ((uint2*)hi)[i] = Hh;
    ((uint2*)lo)[i] = Ll;
}

// ============================ HMMA GEMM (R8/R13 measured-best) ============================
constexpr int BM = 128, BN = 128, BK = 32, STAGES = 4;
constexpr int KD = 1024, KE = 3 * KD;
constexpr int ASTG = BM * BK * 2;
constexpr int BSTG = BN * BK * 2;
constexpr int STG = ASTG + BSTG;
constexpr int HG_SMEM = STAGES * STG;    // 65536

__device__ __forceinline__ void load_stage(uint32_t sbase,
        const __half* __restrict__ Ahi, const __half* __restrict__ Alo,
        const __half* __restrict__ Bhi, const __half* __restrict__ Blo,
        int bm, int bn, int k0, int tid) {
    const int p = k0 >> 10;
    const int ko = k0 & (KD - 1);
    const __half* __restrict__ Asrc = (p == 2) ? Alo : Ahi;   // A-pattern hi,hi,lo
    const __half* __restrict__ Bsrc = (p == 1) ? Blo : Bhi;   // B-pattern hi,lo,hi
#pragma unroll
    for (int i = 0; i < 4; i++) {
        int idx = tid + i * 128;
        int row = idx >> 2, c = idx & 3;
        cp16(sbase + swz(row, c), Asrc + (size_t)(bm + row) * KD + ko + c * 8);
    }
#pragma unroll
    for (int i = 0; i < 4; i++) {
        int idx = tid + i * 128;
        int row = idx >> 2, c = idx & 3;
        cp16(sbase + ASTG + swz(row, c), Bsrc + (size_t)(bn + row) * KD + ko + c * 8);
    }
}

// EPI 0: +bias -> softmax(64-col groups) -> hi/lo planes; EPI 2: +bias -> gelu -> fp32
template <int EPI>
__global__ __launch_bounds__(128, 2)
void hgemm(const __half* __restrict__ Ahi, const __half* __restrict__ Alo,
           const __half* __restrict__ Bhi, const __half* __restrict__ Blo,
           const float* __restrict__ bias,
           __half* __restrict__ Ohi, __half* __restrict__ Olo,
           float* __restrict__ Of32, int Nout) {
    extern __shared__ char smraw[];
    const uint32_t sbase = smem_u32(smraw);
    const int tid = threadIdx.x;
    const int lane = tid & 31, wid = tid >> 5;
    const int wm = wid & 1, wn = wid >> 1;
    const int bm = blockIdx.y * BM, bn = blockIdx.x * BN;

    float acc[4][8][4] = {};
    constexpr int KT = KE / BK;   // 96

#pragma unroll
    for (int s = 0; s < STAGES - 1; s++) {
        load_stage(sbase + s * STG, Ahi, Alo, Bhi, Blo, bm, bn, s * BK, tid);
        CP_COMMIT();
    }

    for (int it = 0; it < KT; it++) {
        CP_WAIT2();
        __syncthreads();
        int nit = it + STAGES - 1;
        if (nit < KT)
            load_stage(sbase + (nit & (STAGES - 1)) * STG, Ahi, Alo, Bhi, Blo,
                       bm, bn, nit * BK, tid);
        CP_COMMIT();

        uint32_t sA = sbase + (it & (STAGES - 1)) * STG;
        uint32_t sB = sA + ASTG;
#pragma unroll
        for (int ks = 0; ks < 2; ks++) {
            uint32_t af[4][4];
#pragma unroll
            for (int mt = 0; mt < 4; mt++) {
                uint32_t row = wm * 64 + mt * 16 + (lane & 15);
                uint32_t ch = ks * 2 + (lane >> 4);
                ldsm4(af[mt][0], af[mt][1], af[mt][2], af[mt][3], sA + swz(row, ch));
            }
            uint32_t bf[4][4];
#pragma unroll
            for (int np = 0; np < 4; np++) {
                uint32_t row = wn * 64 + np * 16 + (lane & 7) + ((lane >> 4) & 1) * 8;
                uint32_t ch = ks * 2 + ((lane >> 3) & 1);
                ldsm4(bf[np][0], bf[np][1], bf[np][2], bf[np][3], sB + swz(row, ch));
            }
#pragma unroll
            for (int mt = 0; mt < 4; mt++)
#pragma unroll
                for (int nt = 0; nt < 8; nt++)
                    mma16816(acc[mt][nt], af[mt], &bf[nt >> 1][(nt & 1) * 2]);
        }
    }

    // ---------------- epilogue ----------------
    const int colb = bn + wn * 64;
    float bv[16];
#pragma unroll
    for (int nt = 0; nt < 8; nt++) {
        int c = colb + nt * 8 + (lane & 3) * 2;
        bv[nt * 2] = bias[c];
        bv[nt * 2 + 1] = bias[c + 1];
    }

#pragma unroll
    for (int mt = 0; mt < 4; mt++) {
#pragma unroll
        for (int h = 0; h < 2; h++) {
            int row = bm + wm * 64 + mt * 16 + (lane >> 2) + h * 8;
            float v[16];
#pragma unroll
            for (int nt = 0; nt < 8; nt++) {
                v[nt * 2] = acc[mt][nt][h * 2] + bv[nt * 2];
                v[nt * 2 + 1] = acc[mt][nt][h * 2 + 1] + bv[nt * 2 + 1];
            }
            if (EPI == 0) {
                float m = v[0];
#pragma unroll
                for (int j = 1; j < 16; j++) m = fmaxf(m, v[j]);
                m = fmaxf(m, __shfl_xor_sync(0xffffffffu, m, 1));
                m = fmaxf(m, __shfl_xor_sync(0xffffffffu, m, 2));
                float s = 0.f;
#pragma unroll
                for (int j = 0; j < 16; j++) { v[j] = expf(v[j] - m); s += v[j]; }
                s += __shfl_xor_sync(0xffffffffu, s, 1);
                s += __shfl_xor_sync(0xffffffffu, s, 2);
                float inv = 1.0f / s;
#pragma unroll
                for (int j = 0; j < 16; j++) v[j] *= inv;
            }
            if (EPI == 2) {
#pragma unroll
                for (int j = 0; j < 16; j++)
                    v[j] = 0.5f * v[j] * (1.0f + erff(v[j] * 0.70710678118654752f));
            }
            if (EPI == 2) {
                float* op = Of32 + (size_t)row * Nout;
#pragma unroll
                for (int nt = 0; nt < 8; nt++) {
                    int c = colb + nt * 8 + (lane & 3) * 2;
                    float2 f2; f2.x = v[nt * 2]; f2.y = v[nt * 2 + 1];
                    *(float2*)(op + c) = f2;
                }
            } else {
                __half* oh = Ohi + (size_t)row * Nout;
                __half* ol = Olo + (size_t)row * Nout;
#pragma unroll
                for (int nt = 0; nt < 8; nt++) {
                    int c = colb + nt * 8 + (lane & 3) * 2;
                    float a = v[nt * 2], b = v[nt * 2 + 1];
                    __half ha = __float2half_rn(a), hb = __float2half_rn(b);
                    __half la = __float2half_rn(a - __half2float(ha));
                    __half lb = __float2half_rn(b - __half2float(hb));
                    *(uint32_t*)(oh + c) = packh2(ha, hb);
                    *(uint32_t*)(ol + c) = packh2(la, lb);
                }
            }
        }
    }
}

// ============================ fused logits + top-2 ============================
__device__ __forceinline__ bool better(float va, int ia, float vb, int ib) {
    return (va > vb) || (va == vb && ia < ib);
}

__global__ __launch_bounds__(256)
void logits_topk_kernel(const float* __restrict__ Hm, const float* __restrict__ W2,
                        const float* __restrict__ b2, float* __restrict__ out, int T) {
    extern __shared__ float w2s[];     // [GH][NE] = 64KB
    __shared__ float b2s[NE];
    for (int i = threadIdx.x; i < NE * GH; i += 256) {
        int e = i >> 8, k = i & (GH - 1);
        w2s[k * NE + e] = W2[i];
    }
    if (threadIdx.x < NE) b2s[threadIdx.x] = b2[threadIdx.x];
    __syncthreads();

    const int wid = threadIdx.x >> 5, lane = threadIdx.x & 31;
#pragma unroll 1
    for (int ti = 0; ti < 16; ti++) {
        const int t = blockIdx.x * 128 + wid * 16 + ti;
        const float* hrow = Hm + (size_t)t * GH;
        float a0 = b2s[lane], a1 = b2s[lane + 32];
#pragma unroll 4
        for (int k4 = 0; k4 < GH / 4; k4++) {
            float4 hv = ((const float4*)hrow)[k4];
            const float* wp = w2s + (k4 * 4) * NE;
            a0 = fmaf(hv.x, wp[lane], a0);
            a1 = fmaf(hv.x, wp[lane + 32], a1);
            a0 = fmaf(hv.y, wp[NE + lane], a0);
            a1 = fmaf(hv.y, wp[NE + lane + 32], a1);
            a0 = fmaf(hv.z, wp[2 * NE + lane], a0);
            a1 = fmaf(hv.z, wp[2 * NE + lane + 32], a1);
            a0 = fmaf(hv.w, wp[3 * NE + lane], a0);
            a1 = fmaf(hv.w, wp[3 * NE + lane + 32], a1);
        }
        float m = fmaxf(a0, a1);
#pragma unroll
        for (int o = 16; o; o >>= 1) m = fmaxf(m, __shfl_xor_sync(0xffffffffu, m, o));
        float Z = expf(a0 - m) + expf(a1 - m);
#pragma unroll
        for (int o = 16; o; o >>= 1) Z += __shfl_xor_sync(0xffffffffu, Z, o);

        float v1, v2; int i1, i2;
        if (a1 > a0) { v1 = a1; i1 = lane + 32; v2 = a0; i2 = lane; }
        else         { v1 = a0; i1 = lane;      v2 = a1; i2 = lane + 32; }
#pragma unroll
        for (int o = 16; o; o >>= 1) {
            float w1 = __shfl_xor_sync(0xffffffffu, v1, o);
            int   j1 = __shfl_xor_sync(0xffffffffu, i1, o);
            float w2v = __shfl_xor_sync(0xffffffffu, v2, o);
            int   j2 = __shfl_xor_sync(0xffffffffu, i2, o);
            if (better(w1, j1, v1, i1)) {
                if (better(v1, i1, w2v, j2)) { v2 = v1; i2 = i1; }
                else                         { v2 = w2v; i2 = j2; }
                v1 = w1; i1 = j1;
            } else {
                if (better(w1, j1, v2, i2)) { v2 = w1; i2 = j1; }
            }
        }
        if (lane == 0) {
            float p1 = expf(v1 - m) / Z;
            float p2 = expf(v2 - m) / Z;
            float denom = p1 + p2 + 1e-8f;
            out[(size_t)t * 2 + 0] = (float)i1;
            out[(size_t)t * 2 + 1] = (float)i2;
            out[(size_t)2 * T + (size_t)t * 2 + 0] = p1 / denom;
            out[(size_t)2 * T + (size_t)t * 2 + 1] = p2 / denom;
        }
    }
}

// ============================ launch ============================
extern "C" void kernel_launch(void* const* d_in, const int* in_sizes, int n_in,
                              void* d_out, int out_size) {
    const float* x   = (const float*)d_in[0];
    const float* emb = (const float*)d_in[1];
    const float* ipw = (const float*)d_in[2];
    const float* ipb = (const float*)d_in[3];
    const float* opw = (const float*)d_in[4];
    const float* opb = (const float*)d_in[5];
    const float* gw1 = (const float*)d_in[6];
    const float* gb1 = (const float*)d_in[7];
    const float* gw2 = (const float*)d_in[8];
    const float* gb2 = (const float*)d_in[9];

    const int T = in_sizes[0] / D;

    cudaFuncSetAttribute(hgemm<0>, cudaFuncAttributeMaxDynamicSharedMemorySize, HG_SMEM);
    cudaFuncSetAttribute(hgemm<2>, cudaFuncAttributeMaxDynamicSharedMemorySize, HG_SMEM);
    const int LT_SMEM = NE * GH * 4;
    cudaFuncSetAttribute(logits_topk_kernel, cudaFuncAttributeMaxDynamicSharedMemorySize, LT_SMEM);

    float *psb, *pb1f, *pH;
    cudaGetSymbolAddress((void**)&psb,  g_sb);
    cudaGetSymbolAddress((void**)&pb1f, g_b1f);
    cudaGetSymbolAddress((void**)&pH,   g_H);
    __half *pxh, *pxl, *pPh, *pPl, *pAwh, *pAwl, *pG1h, *pG1l;
    cudaGetSymbolAddress((void**)&pxh,  g_xh);
    cudaGetSymbolAddress((void**)&pxl,  g_xl);
    cudaGetSymbolAddress((void**)&pPh,  g_Ph);
    cudaGetSymbolAddress((void**)&pPl,  g_Pl);
    cudaGetSymbolAddress((void**)&pAwh, g_Awh);
    cudaGetSymbolAddress((void**)&pAwl, g_Awl);
    cudaGetSymbolAddress((void**)&pG1h, g_G1h);
    cudaGetSymbolAddress((void**)&pG1l, g_G1l);

    // 0: kv(v2)   1: buildA(v2)   2: split x   3: hgemm<0>  <- ncu lands on idx 3
    kv_kernel<<<D / 4, 256>>>(emb, ipw + (size_t)D * D, ipb + D,
                              ipw + (size_t)2 * D * D, ipb + 2 * D);
    buildA_kernel<<<dim3(16, 16), 256>>>(ipw, ipb);
    split_kernel<<<(T * D / 4 + 255) / 256, 256>>>(x, pxh, pxl, T * D / 4);

    hgemm<0><<<dim3(D / BN, T / BM), 128, HG_SMEM>>>(
        pxh, pxl, pAwh, pAwl, psb, pPh, pPl, nullptr, D);

    // 4-6: fold out-proj through gate layer 1 (R13 versions)
    buildMT_kernel<<<D, 256>>>(opw);
    g1_kernel<<<dim3(D / 128, GH / 16), 256>>>(gw1);
    b1fold_kernel<<<GH / 8, 256>>>(gw1, opb, gb1);

    // 7: H = gelu(P·G1^T + b1') -> fp32
    hgemm<2><<<dim3(GH / BN, T / BM), 128, HG_SMEM>>>(
        pPh, pPl, pG1h, pG1l, pb1f, nullptr, nullptr, pH, GH);

    // 8: logits + softmax + top-2 fused
    logits_topk_kernel<<<T / 128, 256, LT_SMEM>>>(pH, gw2, gb2, (float*)d_out, T);
}